// round 5
// baseline (speedup 1.0000x reference)
#include <cuda_runtime.h>

// SequentialConv: B=8, C=64, H=192, W=256, 3x3, sequential row recurrence.
// Persistent wavefront: 8 batches x 16 width-tiles = 128 CTAs (all resident).
// Round 5: float2 input LDS (crossbar below FMA floor), 5-slot ring buffer
// (3 updated + 2 orig) cutting barriers 4->2/step, distributed halo spin,
// bias hoisted to registers.

#define Bb 8
#define Cc 64
#define Hh 192
#define Ww 256
#define NT 16
#define TW 16
#define NTHR 256
#define RST 20         // smem row stride in floats (18 used: w0-1 .. w0+16)

#define WSM_FLOATS (Cc * Cc * 9)
#define RBUF_FLOATS (5 * Cc * RST)     // U0,U1,U2 (updated ring) + O0,O1 (orig)
#define SMEM_BYTES ((WSM_FLOATS + RBUF_FLOATS) * 4)

__device__ int g_flags[Bb * NT];

__global__ void sc_init_flags() {
    int i = threadIdx.x;
    if (i < Bb * NT) g_flags[i] = 1;   // rows 0,1 are complete (unchanged)
}

__global__ void __launch_bounds__(NTHR, 1) sc_main(
    const float* __restrict__ X, const float* __restrict__ Wt,
    const float* __restrict__ Bs, float* __restrict__ Out)
{
    extern __shared__ float smem[];
    float* wsm  = smem;                      // [ci][kh][kw][co]
    float* rbuf = smem + WSM_FLOATS;         // 5 slots of [ci][RST]

    const int tile = blockIdx.x;
    const int b    = blockIdx.y;
    const int w0   = tile * TW;
    const int tid  = threadIdx.x;

    // Weights transposed: wsm[((ci*3+kh)*3+kw)*64 + co] = W[co][ci][kh][kw]
    for (int i = tid; i < Cc * Cc * 9; i += NTHR) {
        int co = i & 63; int r = i >> 6;
        int kw = r % 3; r /= 3; int kh = r % 3; int ci = r / 3;
        wsm[((ci * 3 + kh) * 3 + kw) * Cc + co] = Wt[((co * Cc + ci) * 3 + kh) * 3 + kw];
    }

    const float* Xb = X   + (size_t)b * Cc * Hh * Ww;
    float*       Ob = Out + (size_t)b * Cc * Hh * Ww;

    // Rows 0,1 (unchanged) -> U0,U1 (with halo), copy to Out.
    for (int r = 0; r < 2; r++) {
        for (int i = tid; i < Cc * 18; i += NTHR) {
            int ci = i / 18, wi = i % 18; int w = w0 - 1 + wi;
            float v = (w >= 0 && w < Ww) ? Xb[(ci * Hh + r) * Ww + w] : 0.f;
            rbuf[(r * Cc + ci) * RST + wi] = v;
        }
        for (int i = tid; i < Cc * TW; i += NTHR) {
            int ci = i / TW, wq = i % TW;
            Ob[(ci * Hh + r) * Ww + w0 + wq] = Xb[(ci * Hh + r) * Ww + w0 + wq];
        }
    }
    // Zero U2 halo columns (edge tiles keep them 0 forever; interior tiles
    // overwrite them every step in the halo phase).
    if (tid < Cc) {
        rbuf[(2 * Cc + tid) * RST + 0]  = 0.f;
        rbuf[(2 * Cc + tid) * RST + 17] = 0.f;
    }
    // Orig row 2 -> O0.
    for (int i = tid; i < Cc * 18; i += NTHR) {
        int ci = i / 18, wi = i % 18; int w = w0 - 1 + wi;
        float v = (w >= 0 && w < Ww) ? Xb[(ci * Hh + 2) * Ww + w] : 0.f;
        rbuf[(3 * Cc + ci) * RST + wi] = v;
    }

    // Thread -> (2 output channels, 2 output columns)
    const int co0 = (tid >> 3) * 2;      // 32 co-groups of 2
    const int wl  = (tid & 7) * 2;       // 8 w-groups of 2 (even -> float2 aligned)
    const float bb0 = __ldg(&Bs[co0]);
    const float bb1 = __ldg(&Bs[co0 + 1]);

    int* myflag = &g_flags[b * NT + tile];
    int* lflag  = (tile > 0)      ? &g_flags[b * NT + tile - 1] : (int*)0;
    int* rflag  = (tile < NT - 1) ? &g_flags[b * NT + tile + 1] : (int*)0;

    __syncthreads();

    for (int pos = 2; pos < Hh; pos++) {
        const int s0i = (pos + 1) % 3;           // updated row pos-2
        const int s1i = (pos + 2) % 3;           // updated row pos-1
        const int s2i = pos % 3;                 // updated row pos (write)
        float*       s2 = rbuf + s2i * Cc * RST;
        const float* po = rbuf + (3 + (pos & 1)) * Cc * RST;        // orig row pos
        float*       pn = rbuf + (3 + ((pos + 1) & 1)) * Cc * RST;  // next orig (dead slot)

        // Prefetch next orig row early (latency overlapped with compute).
        float pv[5];
        if (pos + 1 < Hh) {
            #pragma unroll
            for (int k = 0; k < 5; k++) {
                int idx = tid + k * NTHR;
                if (idx < Cc * 18) {
                    int ci = idx / 18, wi = idx % 18; int w = w0 - 1 + wi;
                    pv[k] = (w >= 0 && w < Ww) ? __ldg(&Xb[(ci * Hh + pos + 1) * Ww + w]) : 0.f;
                }
            }
        }

        float acc0[2] = {0.f, 0.f};
        float acc1[2] = {0.f, 0.f};
        const float* b0r = rbuf + s0i * Cc * RST + wl;
        const float* b1r = rbuf + s1i * Cc * RST + wl;
        const float* b2r = po + wl;
        const float* wq  = wsm + co0;

        #pragma unroll 4
        for (int ci = 0; ci < Cc; ci++) {
            #pragma unroll
            for (int kh = 0; kh < 3; kh++) {
                const float* row = (kh == 0 ? b0r : kh == 1 ? b1r : b2r) + ci * RST;
                float2 pA = *(const float2*)(row);        // in[wl], in[wl+1]
                float2 pB = *(const float2*)(row + 2);    // in[wl+2], in[wl+3]
                const float* wk = wq + (ci * 9 + kh * 3) * Cc;
                float2 wv0 = *(const float2*)(wk);
                float2 wv1 = *(const float2*)(wk + Cc);
                float2 wv2 = *(const float2*)(wk + 2 * Cc);
                acc0[0] += pA.x * wv0.x; acc1[0] += pA.x * wv0.y;
                acc0[1] += pA.y * wv0.x; acc1[1] += pA.y * wv0.y;
                acc0[0] += pA.y * wv1.x; acc1[0] += pA.y * wv1.y;
                acc0[1] += pB.x * wv1.x; acc1[1] += pB.x * wv1.y;
                acc0[0] += pB.x * wv2.x; acc1[0] += pB.x * wv2.y;
                acc0[1] += pB.y * wv2.x; acc1[1] += pB.y * wv2.y;
            }
        }

        // res = orig + tanh(y + bias); orig read from po (separate slot, no hazard).
        float res0[2], res1[2];
        {
            const float* o0 = po + co0 * RST + wl + 1;
            const float* o1 = o0 + RST;
            res0[0] = o0[0] + tanhf(acc0[0] + bb0);
            res0[1] = o0[1] + tanhf(acc0[1] + bb0);
            res1[0] = o1[0] + tanhf(acc1[0] + bb1);
            res1[1] = o1[1] + tanhf(acc1[1] + bb1);
        }

        // Write updated row to s2 interior + Out; store prefetched orig to pn.
        float* wr = s2 + co0 * RST + wl + 1;
        wr[0] = res0[0]; wr[1] = res0[1];
        wr[RST] = res1[0]; wr[RST + 1] = res1[1];

        float* og = Ob + ((size_t)co0 * Hh + pos) * Ww + w0 + wl;
        *(float2*)og = make_float2(res0[0], res0[1]);
        *(float2*)(og + (size_t)Hh * Ww) = make_float2(res1[0], res1[1]);

        if (pos + 1 < Hh) {
            #pragma unroll
            for (int k = 0; k < 5; k++) {
                int idx = tid + k * NTHR;
                if (idx < Cc * 18) {
                    int ci = idx / 18, wi = idx % 18;
                    pn[ci * RST + wi] = pv[k];
                }
            }
        }

        // Publish: fence (global visibility) -> barrier -> flag release.
        __threadfence();
        __syncthreads();
        if (tid == 0) atomicExch(myflag, pos);

        // Halo acquire for s2: warps 0-1 spin+load left, warps 6-7 right.
        if (tid < Cc) {
            if (lflag) {
                while (*(volatile int*)lflag < pos) __nanosleep(40);
                __threadfence();
                s2[tid * RST + 0] = __ldcg(&Ob[((size_t)tid * Hh + pos) * Ww + w0 - 1]);
            }
        } else if (tid >= NTHR - Cc) {
            int ci = tid - (NTHR - Cc);
            if (rflag) {
                while (*(volatile int*)rflag < pos) __nanosleep(40);
                __threadfence();
                s2[ci * RST + 17] = __ldcg(&Ob[((size_t)ci * Hh + pos) * Ww + w0 + TW]);
            }
        }
        __syncthreads();   // s2 halos + pn visible for next step
    }
}

extern "C" void kernel_launch(void* const* d_in, const int* in_sizes, int n_in,
                              void* d_out, int out_size) {
    const float* X  = (const float*)d_in[0];
    const float* Wt = (const float*)d_in[1];
    const float* Bs = (const float*)d_in[2];
    float* Out = (float*)d_out;
    (void)in_sizes; (void)n_in; (void)out_size;

    cudaFuncSetAttribute(sc_main, cudaFuncAttributeMaxDynamicSharedMemorySize, SMEM_BYTES);

    sc_init_flags<<<1, 128>>>();
    sc_main<<<dim3(NT, Bb), NTHR, SMEM_BYTES>>>(X, Wt, Bs, Out);
}

// round 7
// speedup vs baseline: 1.1108x; 1.1108x over previous
#include <cuda_runtime.h>

// SequentialConv: B=8, C=64, H=192, W=256, 3x3, sequential row recurrence.
// Persistent wavefront: 8 batches x 16 width-tiles = 128 CTAs (all resident).
// Round 7: R6 retry with 20-float (80B, 16-aligned) weight records fixing the
// LDS.128 misalignment; 2 barriers/step; halo spin overlapped with orig STS.

#define Bb 8
#define Cc 64
#define Hh 192
#define Ww 256
#define NT 16
#define TW 16
#define NTHR 256
#define RST 20          // smem row stride in floats (18 used: w0-1 .. w0+16)
#define WREC 20         // padded weight record: 18 used + 2 pad (80 B, 16-aligned)

#define WSM_FLOATS (Cc * 32 * WREC)     // [ci][cp][WREC]
#define RBUF_FLOATS (5 * Cc * RST)      // U0,U1,U2 ring + O0,O1 pingpong
#define SMEM_BYTES ((WSM_FLOATS + RBUF_FLOATS) * 4)

__device__ int g_flags[Bb * NT];

__global__ void sc_init_flags() {
    int i = threadIdx.x;
    if (i < Bb * NT) g_flags[i] = 0;
}

__global__ void __launch_bounds__(NTHR, 1) sc_main(
    const float* __restrict__ X, const float* __restrict__ Wt,
    const float* __restrict__ Bs, float* __restrict__ Out)
{
    extern __shared__ float smem[];
    float* wsm  = smem;                       // [(ci*32+cp)*WREC + (kh*3+kw)*2 + c]
    float* ubuf = smem + WSM_FLOATS;          // U0..U2: updated-row ring
    float* obuf = ubuf + 3 * Cc * RST;        // O0,O1: orig-row pingpong

    const int tile = blockIdx.x;
    const int b    = blockIdx.y;
    const int w0   = tile * TW;
    const int tid  = threadIdx.x;

    // Weights: one 18-used-float record per (ci, co-pair), stride WREC.
    for (int i = tid; i < Cc * 32 * 18; i += NTHR) {
        int j = i % 18; int r = i / 18;
        int cp = r & 31; int ci = r >> 5;
        int c = j & 1; int khkw = j >> 1;
        int kh = khkw / 3, kw = khkw % 3;
        int co = cp * 2 + c;
        wsm[r * WREC + j] = Wt[((co * Cc + ci) * 3 + kh) * 3 + kw];
    }

    const float* Xb = X   + (size_t)b * Cc * Hh * Ww;
    float*       Ob = Out + (size_t)b * Cc * Hh * Ww;

    // Rows 0,1 (unchanged) -> U0,U1 with halo; copy to Out. Zero U2 halo cols.
    for (int r = 0; r < 2; r++) {
        for (int i = tid; i < Cc * 18; i += NTHR) {
            int ci = i / 18, wi = i % 18; int w = w0 - 1 + wi;
            float v = (w >= 0 && w < Ww) ? Xb[(ci * Hh + r) * Ww + w] : 0.f;
            ubuf[(r * Cc + ci) * RST + wi] = v;
        }
        for (int i = tid; i < Cc * TW; i += NTHR) {
            int ci = i / TW, wq = i % TW;
            Ob[(ci * Hh + r) * Ww + w0 + wq] = Xb[(ci * Hh + r) * Ww + w0 + wq];
        }
    }
    if (tid < Cc) {
        ubuf[(2 * Cc + tid) * RST + 0]  = 0.f;
        ubuf[(2 * Cc + tid) * RST + 17] = 0.f;
    }

    // Thread -> (co pair cp, 2 output columns at wl2)
    const int cp  = tid >> 3;            // 0..31
    const int co0 = cp * 2;
    const int wl2 = (tid & 7) * 2;       // 0..14, even
    const float bb0 = __ldg(&Bs[co0]);
    const float bb1 = __ldg(&Bs[co0 + 1]);

    int* myflag = &g_flags[b * NT + tile];
    int* lflag  = (tile > 0)      ? &g_flags[b * NT + tile - 1] : (int*)0;
    int* rflag  = (tile < NT - 1) ? &g_flags[b * NT + tile + 1] : (int*)0;

    // Publish rows 0,1 (flag=1) only after they are globally visible.
    __threadfence();
    __syncthreads();
    if (tid == 0) atomicExch(myflag, 1);

    // Prefetch orig row 2 into registers (5 elems/thread covers 64*18=1152).
    float pv[5];
    #pragma unroll
    for (int k = 0; k < 5; k++) {
        int idx = tid + k * NTHR;
        if (idx < Cc * 18) {
            int ci = idx / 18, wi = idx % 18; int w = w0 - 1 + wi;
            pv[k] = (w >= 0 && w < Ww) ? __ldg(&Xb[(ci * Hh + 2) * Ww + w]) : 0.f;
        }
    }

    for (int pos = 2; pos < Hh; pos++) {
        float*       sU2 = ubuf + (pos % 3) * Cc * RST;        // write: row pos
        const float* sU0 = ubuf + ((pos + 1) % 3) * Cc * RST;  // row pos-2
        float*       sU1 = ubuf + ((pos + 2) % 3) * Cc * RST;  // row pos-1 (halo lands here)
        float*       sO  = obuf + (pos & 1) * Cc * RST;        // orig row pos

        // Store prefetched orig row pos.
        #pragma unroll
        for (int k = 0; k < 5; k++) {
            int idx = tid + k * NTHR;
            if (idx < Cc * 18) {
                int ci = idx / 18, wi = idx % 18;
                sO[ci * RST + wi] = pv[k];
            }
        }
        // Halo acquire for row pos-1 into sU1 cols 0/17 (overlaps STS above).
        if (tid < Cc) {
            if (lflag) {
                while (*(volatile int*)lflag < pos - 1) __nanosleep(32);
                __threadfence();
                sU1[tid * RST + 0] = __ldcg(&Ob[((size_t)tid * Hh + pos - 1) * Ww + w0 - 1]);
            }
        } else if (tid >= NTHR - Cc) {
            int ci = tid - (NTHR - Cc);
            if (rflag) {
                while (*(volatile int*)rflag < pos - 1) __nanosleep(32);
                __threadfence();
                sU1[ci * RST + 17] = __ldcg(&Ob[((size_t)ci * Hh + pos - 1) * Ww + w0 + TW]);
            }
        }
        __syncthreads();   // orig row + fresh halo visible

        float a00 = 0.f, a01 = 0.f, a10 = 0.f, a11 = 0.f;
        const float* i0 = sU0 + wl2;
        const float* i1 = sU1 + wl2;
        const float* i2 = sO  + wl2;
        const float* wb = wsm + cp * WREC;

        #pragma unroll 2
        for (int ci = 0; ci < Cc; ci++) {
            const float4* wv = (const float4*)(wb + ci * (32 * WREC));
            float4 w0v = wv[0], w1v = wv[1], w2v = wv[2], w3v = wv[3];
            float2 w4v = *(const float2*)(wb + ci * (32 * WREC) + 16);

            float2 pA = *(const float2*)(i0 + ci * RST);
            float2 pB = *(const float2*)(i0 + ci * RST + 2);
            a00 += pA.x * w0v.x; a10 += pA.x * w0v.y;
            a01 += pA.y * w0v.x; a11 += pA.y * w0v.y;
            a00 += pA.y * w0v.z; a10 += pA.y * w0v.w;
            a01 += pB.x * w0v.z; a11 += pB.x * w0v.w;
            a00 += pB.x * w1v.x; a10 += pB.x * w1v.y;
            a01 += pB.y * w1v.x; a11 += pB.y * w1v.y;

            pA = *(const float2*)(i1 + ci * RST);
            pB = *(const float2*)(i1 + ci * RST + 2);
            a00 += pA.x * w1v.z; a10 += pA.x * w1v.w;
            a01 += pA.y * w1v.z; a11 += pA.y * w1v.w;
            a00 += pA.y * w2v.x; a10 += pA.y * w2v.y;
            a01 += pB.x * w2v.x; a11 += pB.x * w2v.y;
            a00 += pB.x * w2v.z; a10 += pB.x * w2v.w;
            a01 += pB.y * w2v.z; a11 += pB.y * w2v.w;

            pA = *(const float2*)(i2 + ci * RST);
            pB = *(const float2*)(i2 + ci * RST + 2);
            a00 += pA.x * w3v.x; a10 += pA.x * w3v.y;
            a01 += pA.y * w3v.x; a11 += pA.y * w3v.y;
            a00 += pA.y * w3v.z; a10 += pA.y * w3v.w;
            a01 += pB.x * w3v.z; a11 += pB.x * w3v.w;
            a00 += pB.x * w4v.x; a10 += pB.x * w4v.y;
            a01 += pB.y * w4v.x; a11 += pB.y * w4v.y;
        }

        // res = orig + tanh(y + bias); orig from separate slot -> no WAR barrier.
        const float* o0 = sO + co0 * RST + wl2 + 1;
        const float* o1 = o0 + RST;
        float r00 = o0[0] + tanhf(a00 + bb0);
        float r01 = o0[1] + tanhf(a01 + bb0);
        float r10 = o1[0] + tanhf(a10 + bb1);
        float r11 = o1[1] + tanhf(a11 + bb1);

        // Write row pos: smem interior (slot held dead row pos-3) + Out.
        float* wr = sU2 + co0 * RST + wl2 + 1;
        wr[0] = r00; wr[1] = r01;
        wr[RST] = r10; wr[RST + 1] = r11;

        float* og = Ob + ((size_t)co0 * Hh + pos) * Ww + w0 + wl2;
        *(float2*)og = make_float2(r00, r01);
        *(float2*)(og + (size_t)Hh * Ww) = make_float2(r10, r11);

        // Prefetch next orig row (overlaps fence/barrier).
        if (pos + 1 < Hh) {
            #pragma unroll
            for (int k = 0; k < 5; k++) {
                int idx = tid + k * NTHR;
                if (idx < Cc * 18) {
                    int ci = idx / 18, wi = idx % 18; int w = w0 - 1 + wi;
                    pv[k] = (w >= 0 && w < Ww) ? __ldg(&Xb[(ci * Hh + pos + 1) * Ww + w]) : 0.f;
                }
            }
        }

        __threadfence();
        __syncthreads();
        if (tid == 0) atomicExch(myflag, pos);
    }
}

extern "C" void kernel_launch(void* const* d_in, const int* in_sizes, int n_in,
                              void* d_out, int out_size) {
    const float* X  = (const float*)d_in[0];
    const float* Wt = (const float*)d_in[1];
    const float* Bs = (const float*)d_in[2];
    float* Out = (float*)d_out;
    (void)in_sizes; (void)n_in; (void)out_size;

    cudaFuncSetAttribute(sc_main, cudaFuncAttributeMaxDynamicSharedMemorySize, SMEM_BYTES);

    sc_init_flags<<<1, 128>>>();
    sc_main<<<dim3(NT, Bb), NTHR, SMEM_BYTES>>>(X, Wt, Bs, Out);
}